// round 1
// baseline (speedup 1.0000x reference)
#include <cuda_runtime.h>
#include <cuda_bf16.h>
#include <cstdint>

// Problem constants (fixed by the reference)
#define NNODES 10000
#define FDIM   256      // feature dim == filters
#define NEDGES 320000

// -------- scratch (device globals; no allocation allowed) --------
__device__ float g_H[NNODES * FDIM];   // ping buffer
__device__ float g_S[NNODES * FDIM];   // pong buffer

// ============================================================================
// Dense GEMM: C[M,256] = A[M,256] @ B[256,256], fp32, row-major.
// 128x128 block tile, BK=16, 256 threads, 8x8 per-thread micro-tile.
// ============================================================================
#define BM 128
#define BN 128
#define BK 16

__global__ __launch_bounds__(256) void sgemm_256(
    const float* __restrict__ A, const float* __restrict__ B,
    float* __restrict__ C, int M)
{
    const int K = 256, N = 256;
    __shared__ float As[BK][BM];
    __shared__ float Bs[BK][BN];

    const int bm = blockIdx.y * BM;
    const int bn = blockIdx.x * BN;
    const int tid = threadIdx.x;

    const int tm = (tid / 16) * 8;     // 0..120
    const int tn = (tid % 16) * 8;     // 0..120

    // A-tile load mapping: 128 rows x 16 cols = 512 float4; 2 per thread
    const int arow = tid / 4;          // 0..63 (two passes of 64 rows)
    const int acol = (tid % 4) * 4;    // 0,4,8,12
    // B-tile load mapping: 16 rows x 128 cols = 512 float4; 2 per thread
    const int brow = tid / 32;         // 0..7 (two passes of 8 rows)
    const int bcol = (tid % 32) * 4;   // 0..124

    float acc[8][8] = {};

    for (int k0 = 0; k0 < K; k0 += BK) {
        #pragma unroll
        for (int p = 0; p < 2; ++p) {
            int r = arow + p * 64;
            int grow = bm + r;
            float4 av = make_float4(0.f, 0.f, 0.f, 0.f);
            if (grow < M)
                av = *reinterpret_cast<const float4*>(A + (size_t)grow * K + k0 + acol);
            As[acol + 0][r] = av.x;
            As[acol + 1][r] = av.y;
            As[acol + 2][r] = av.z;
            As[acol + 3][r] = av.w;
        }
        #pragma unroll
        for (int p = 0; p < 2; ++p) {
            int r = brow + p * 8;
            float4 bv = *reinterpret_cast<const float4*>(B + (size_t)(k0 + r) * N + bn + bcol);
            *reinterpret_cast<float4*>(&Bs[r][bcol]) = bv;
        }
        __syncthreads();

        #pragma unroll
        for (int k = 0; k < BK; ++k) {
            float a[8], b[8];
            *reinterpret_cast<float4*>(&a[0]) = *reinterpret_cast<const float4*>(&As[k][tm]);
            *reinterpret_cast<float4*>(&a[4]) = *reinterpret_cast<const float4*>(&As[k][tm + 4]);
            *reinterpret_cast<float4*>(&b[0]) = *reinterpret_cast<const float4*>(&Bs[k][tn]);
            *reinterpret_cast<float4*>(&b[4]) = *reinterpret_cast<const float4*>(&Bs[k][tn + 4]);
            #pragma unroll
            for (int i = 0; i < 8; ++i)
                #pragma unroll
                for (int j = 0; j < 8; ++j)
                    acc[i][j] = fmaf(a[i], b[j], acc[i][j]);
        }
        __syncthreads();
    }

    #pragma unroll
    for (int i = 0; i < 8; ++i) {
        int grow = bm + tm + i;
        if (grow < M) {
            #pragma unroll
            for (int j = 0; j < 8; j += 4) {
                *reinterpret_cast<float4*>(C + (size_t)grow * N + bn + tn + j) =
                    make_float4(acc[i][j], acc[i][j + 1], acc[i][j + 2], acc[i][j + 3]);
            }
        }
    }
}

// ============================================================================
// SpMM scatter: out[dst] += scale * val * h[src]   (out NOT zeroed here)
// 64 threads per edge, each handles one float4 (256 floats / edge).
// Vector red.global.add.v4.f32 (sm_90+) quarters atomic instruction count.
// ============================================================================
__global__ __launch_bounds__(256) void spmm_scatter(
    const float* __restrict__ h, float* __restrict__ out,
    const int* __restrict__ src, const int* __restrict__ dst,
    const float* __restrict__ vals, int nEdges, float scale)
{
    int t = blockIdx.x * blockDim.x + threadIdx.x;
    int edge = t >> 6;
    int c = (t & 63) << 2;                 // float index within row, 16B aligned
    if (edge >= nEdges) return;

    int s = __ldg(src + edge);
    int d = __ldg(dst + edge);
    float v = __ldg(vals + edge) * scale;

    float4 hv = *reinterpret_cast<const float4*>(h + (size_t)s * FDIM + c);
    float* p = out + (size_t)d * FDIM + c;
    asm volatile("red.global.add.v4.f32 [%0], {%1, %2, %3, %4};"
                 :: "l"(p), "f"(hv.x * v), "f"(hv.y * v), "f"(hv.z * v), "f"(hv.w * v)
                 : "memory");
}

// ============================================================================
// Utility kernels
// ============================================================================
__global__ void zero_f4(float4* __restrict__ p, int n4)
{
    int i = blockIdx.x * blockDim.x + threadIdx.x;
    if (i < n4) p[i] = make_float4(0.f, 0.f, 0.f, 0.f);
}

__global__ void relu_inplace_f4(float4* __restrict__ p, int n4)
{
    int i = blockIdx.x * blockDim.x + threadIdx.x;
    if (i < n4) {
        float4 v = p[i];
        v.x = fmaxf(v.x, 0.f); v.y = fmaxf(v.y, 0.f);
        v.z = fmaxf(v.z, 0.f); v.w = fmaxf(v.w, 0.f);
        p[i] = v;
    }
}

// ============================================================================
// Launch:  out = relu( (1/3) * A*(h1 + A*(h2 + A*h3)) )
//   where hk = x @ Wk.   (Horner form of f1+f2+f3 — 3 SpMMs instead of 6.)
// Sequence (default stream, in-order):
//   1. g_H = x @ W3
//   2. g_S = x @ W2
//   3. g_S += A @ g_H          (atomic scatter)
//   4. g_H = x @ W1            (after step 3 finished reading g_H)
//   5. g_H += A @ g_S
//   6. d_out = 0
//   7. d_out += (1/3) A @ g_H
//   8. d_out = relu(d_out)
// ============================================================================
extern "C" void kernel_launch(void* const* d_in, const int* in_sizes, int n_in,
                              void* d_out, int out_size)
{
    const float* x      = (const float*)d_in[0];
    const float* A_vals = (const float*)d_in[1];
    const float* W1     = (const float*)d_in[2];
    const float* W2     = (const float*)d_in[3];
    const float* W3     = (const float*)d_in[4];
    const int*   e_src  = (const int*)d_in[5];
    const int*   e_dst  = (const int*)d_in[6];
    float* out = (float*)d_out;

    const int M = in_sizes[0] / FDIM;      // 10000
    const int E = in_sizes[5];             // 320000

    float* H; float* S;
    cudaGetSymbolAddress((void**)&H, g_H);
    cudaGetSymbolAddress((void**)&S, g_S);

    dim3 gemmGrid(256 / BN, (M + BM - 1) / BM);
    dim3 gemmBlk(256);
    const int spmmBlocks = (E * 64 + 255) / 256;
    const int n4 = M * FDIM / 4;
    const int utilBlocks = (n4 + 255) / 256;

    // 1-2: branch projections
    sgemm_256<<<gemmGrid, gemmBlk>>>(x, W3, H, M);
    sgemm_256<<<gemmGrid, gemmBlk>>>(x, W2, S, M);
    // 3: S = h2 + A*h3
    spmm_scatter<<<spmmBlocks, 256>>>(H, S, e_src, e_dst, A_vals, E, 1.0f);
    // 4: H = h1
    sgemm_256<<<gemmGrid, gemmBlk>>>(x, W1, H, M);
    // 5: H = h1 + A*(h2 + A*h3)
    spmm_scatter<<<spmmBlocks, 256>>>(S, H, e_src, e_dst, A_vals, E, 1.0f);
    // 6-8: out = relu( (1/3) * A * H )
    zero_f4<<<utilBlocks, 256>>>((float4*)out, n4);
    spmm_scatter<<<spmmBlocks, 256>>>(H, out, e_src, e_dst, A_vals, E, 1.0f / 3.0f);
    relu_inplace_f4<<<utilBlocks, 256>>>((float4*)out, n4);
}

// round 2
// speedup vs baseline: 1.8020x; 1.8020x over previous
#include <cuda_runtime.h>
#include <cuda_bf16.h>
#include <cstdint>

#define NNODES 10000
#define FDIM   256
#define NEDGES 320000

// -------- scratch (device globals; no allocation allowed) --------
__device__ float g_H1[NNODES * FDIM];
__device__ float g_H2[NNODES * FDIM];
__device__ float g_H3[NNODES * FDIM];
__device__ int   g_cnt[NNODES];
__device__ int   g_offs[NNODES + 1];
__device__ int   g_cur[NNODES];
__device__ int   g_psrc[NEDGES];
__device__ float g_pval[NEDGES];

// ============================================================================
// Fused triple GEMM: Hk[M,256] = x[M,256] @ Wk[256,256] for k=1..3.
// blockIdx.x in [0,6): which W / which 128-col half. 128x128 tile, BK=16.
// ============================================================================
#define BM 128
#define BN 128
#define BK 16

__global__ __launch_bounds__(256) void sgemm3(
    const float* __restrict__ A,
    const float* __restrict__ B0, const float* __restrict__ B1, const float* __restrict__ B2,
    float* __restrict__ C0, float* __restrict__ C1, float* __restrict__ C2,
    int M)
{
    const int K = 256, N = 256;
    const int which = blockIdx.x >> 1;
    const float* B = (which == 0) ? B0 : (which == 1) ? B1 : B2;
    float*       C = (which == 0) ? C0 : (which == 1) ? C1 : C2;

    __shared__ float As[BK][BM];
    __shared__ float Bs[BK][BN];

    const int bm = blockIdx.y * BM;
    const int bn = (blockIdx.x & 1) * BN;
    const int tid = threadIdx.x;

    const int tm = (tid / 16) * 8;
    const int tn = (tid % 16) * 8;

    const int arow = tid / 4;
    const int acol = (tid % 4) * 4;
    const int brow = tid / 32;
    const int bcol = (tid % 32) * 4;

    float acc[8][8] = {};

    for (int k0 = 0; k0 < K; k0 += BK) {
        #pragma unroll
        for (int p = 0; p < 2; ++p) {
            int r = arow + p * 64;
            int grow = bm + r;
            float4 av = make_float4(0.f, 0.f, 0.f, 0.f);
            if (grow < M)
                av = *reinterpret_cast<const float4*>(A + (size_t)grow * K + k0 + acol);
            As[acol + 0][r] = av.x;
            As[acol + 1][r] = av.y;
            As[acol + 2][r] = av.z;
            As[acol + 3][r] = av.w;
        }
        #pragma unroll
        for (int p = 0; p < 2; ++p) {
            int r = brow + p * 8;
            float4 bv = *reinterpret_cast<const float4*>(B + (size_t)(k0 + r) * N + bn + bcol);
            *reinterpret_cast<float4*>(&Bs[r][bcol]) = bv;
        }
        __syncthreads();

        #pragma unroll
        for (int k = 0; k < BK; ++k) {
            float a[8], b[8];
            *reinterpret_cast<float4*>(&a[0]) = *reinterpret_cast<const float4*>(&As[k][tm]);
            *reinterpret_cast<float4*>(&a[4]) = *reinterpret_cast<const float4*>(&As[k][tm + 4]);
            *reinterpret_cast<float4*>(&b[0]) = *reinterpret_cast<const float4*>(&Bs[k][tn]);
            *reinterpret_cast<float4*>(&b[4]) = *reinterpret_cast<const float4*>(&Bs[k][tn + 4]);
            #pragma unroll
            for (int i = 0; i < 8; ++i)
                #pragma unroll
                for (int j = 0; j < 8; ++j)
                    acc[i][j] = fmaf(a[i], b[j], acc[i][j]);
        }
        __syncthreads();
    }

    #pragma unroll
    for (int i = 0; i < 8; ++i) {
        int grow = bm + tm + i;
        if (grow < M) {
            #pragma unroll
            for (int j = 0; j < 8; j += 4) {
                *reinterpret_cast<float4*>(C + (size_t)grow * N + bn + tn + j) =
                    make_float4(acc[i][j], acc[i][j + 1], acc[i][j + 2], acc[i][j + 3]);
            }
        }
    }
}

// ============================================================================
// CSR build: histogram -> single-block exclusive scan -> stable-ish scatter
// (permutes src & val into contiguous per-dst runs)
// ============================================================================
__global__ void zero_counts(int* __restrict__ cnt, int n)
{
    int i = blockIdx.x * blockDim.x + threadIdx.x;
    if (i < n) cnt[i] = 0;
}

__global__ void hist_dst(const int* __restrict__ dst, int* __restrict__ cnt, int E)
{
    int e = blockIdx.x * blockDim.x + threadIdx.x;
    if (e < E) atomicAdd(&cnt[dst[e]], 1);
}

__global__ __launch_bounds__(1024) void scan_offsets(
    const int* __restrict__ cnt, int* __restrict__ offs, int* __restrict__ cur, int n)
{
    __shared__ int sh[1024];
    __shared__ int s_carry;
    if (threadIdx.x == 0) s_carry = 0;
    __syncthreads();

    for (int base = 0; base < n; base += 1024) {
        int i = base + threadIdx.x;
        int v = (i < n) ? cnt[i] : 0;
        sh[threadIdx.x] = v;
        __syncthreads();
        // Hillis-Steele inclusive scan
        #pragma unroll
        for (int d = 1; d < 1024; d <<= 1) {
            int t = (threadIdx.x >= d) ? sh[threadIdx.x - d] : 0;
            __syncthreads();
            sh[threadIdx.x] += t;
            __syncthreads();
        }
        int carry = s_carry;
        int excl = carry + sh[threadIdx.x] - v;
        if (i < n) { offs[i] = excl; cur[i] = excl; }
        __syncthreads();
        if (threadIdx.x == 0) s_carry = carry + sh[1023];
        __syncthreads();
    }
    if (threadIdx.x == 0) offs[n] = s_carry;
}

__global__ void scatter_edges(
    const int* __restrict__ src, const int* __restrict__ dst,
    const float* __restrict__ vals, int* __restrict__ cur,
    int* __restrict__ psrc, float* __restrict__ pval, int E)
{
    int e = blockIdx.x * blockDim.x + threadIdx.x;
    if (e < E) {
        int pos = atomicAdd(&cur[dst[e]], 1);
        psrc[pos] = src[e];
        pval[pos] = vals[e];
    }
}

// ============================================================================
// CSR SpMM gather: per dst node, accumulate over its in-edges. No atomics.
// 64 threads per node (float4 each), 4 nodes per 256-thread block.
// mode 0: out[n] += sum_e val_e * h[src_e]   (out pre-holds the "+h" term)
// mode 1: out[n]  = relu( (1/3) * sum_e val_e * h[src_e] )
// ============================================================================
__global__ __launch_bounds__(256) void spmm_csr(
    const float* __restrict__ h, float* __restrict__ outp,
    const int* __restrict__ psrc, const float* __restrict__ pval,
    const int* __restrict__ offs, int M, int finalMode)
{
    int node = blockIdx.x * 4 + (threadIdx.x >> 6);
    if (node >= M) return;
    int c = (threadIdx.x & 63) << 2;

    int beg = __ldg(offs + node);
    int end = __ldg(offs + node + 1);

    float4 acc;
    if (finalMode) acc = make_float4(0.f, 0.f, 0.f, 0.f);
    else           acc = *reinterpret_cast<const float4*>(outp + (size_t)node * FDIM + c);

    int e = beg;
    for (; e + 4 <= end; e += 4) {
        int   s0 = __ldg(psrc + e),     s1 = __ldg(psrc + e + 1);
        int   s2 = __ldg(psrc + e + 2), s3 = __ldg(psrc + e + 3);
        float v0 = __ldg(pval + e),     v1 = __ldg(pval + e + 1);
        float v2 = __ldg(pval + e + 2), v3 = __ldg(pval + e + 3);
        float4 r0 = *reinterpret_cast<const float4*>(h + (size_t)s0 * FDIM + c);
        float4 r1 = *reinterpret_cast<const float4*>(h + (size_t)s1 * FDIM + c);
        float4 r2 = *reinterpret_cast<const float4*>(h + (size_t)s2 * FDIM + c);
        float4 r3 = *reinterpret_cast<const float4*>(h + (size_t)s3 * FDIM + c);
        acc.x = fmaf(v0, r0.x, acc.x); acc.y = fmaf(v0, r0.y, acc.y);
        acc.z = fmaf(v0, r0.z, acc.z); acc.w = fmaf(v0, r0.w, acc.w);
        acc.x = fmaf(v1, r1.x, acc.x); acc.y = fmaf(v1, r1.y, acc.y);
        acc.z = fmaf(v1, r1.z, acc.z); acc.w = fmaf(v1, r1.w, acc.w);
        acc.x = fmaf(v2, r2.x, acc.x); acc.y = fmaf(v2, r2.y, acc.y);
        acc.z = fmaf(v2, r2.z, acc.z); acc.w = fmaf(v2, r2.w, acc.w);
        acc.x = fmaf(v3, r3.x, acc.x); acc.y = fmaf(v3, r3.y, acc.y);
        acc.z = fmaf(v3, r3.z, acc.z); acc.w = fmaf(v3, r3.w, acc.w);
    }
    for (; e < end; ++e) {
        int s = __ldg(psrc + e);
        float v = __ldg(pval + e);
        float4 r = *reinterpret_cast<const float4*>(h + (size_t)s * FDIM + c);
        acc.x = fmaf(v, r.x, acc.x); acc.y = fmaf(v, r.y, acc.y);
        acc.z = fmaf(v, r.z, acc.z); acc.w = fmaf(v, r.w, acc.w);
    }

    if (finalMode) {
        const float third = 1.0f / 3.0f;
        acc.x = fmaxf(acc.x * third, 0.f);
        acc.y = fmaxf(acc.y * third, 0.f);
        acc.z = fmaxf(acc.z * third, 0.f);
        acc.w = fmaxf(acc.w * third, 0.f);
    }
    *reinterpret_cast<float4*>(outp + (size_t)node * FDIM + c) = acc;
}

// ============================================================================
// out = relu( (1/3) * A*(h1 + A*(h2 + A*h3)) ),  hk = x @ Wk   (Horner)
// ============================================================================
extern "C" void kernel_launch(void* const* d_in, const int* in_sizes, int n_in,
                              void* d_out, int out_size)
{
    const float* x      = (const float*)d_in[0];
    const float* A_vals = (const float*)d_in[1];
    const float* W1     = (const float*)d_in[2];
    const float* W2     = (const float*)d_in[3];
    const float* W3     = (const float*)d_in[4];
    const int*   e_src  = (const int*)d_in[5];
    const int*   e_dst  = (const int*)d_in[6];
    float* out = (float*)d_out;

    const int M = in_sizes[0] / FDIM;      // 10000
    const int E = in_sizes[5];             // 320000

    float *H1, *H2, *H3; int *cnt, *offs, *cur, *psrc; float *pval;
    cudaGetSymbolAddress((void**)&H1, g_H1);
    cudaGetSymbolAddress((void**)&H2, g_H2);
    cudaGetSymbolAddress((void**)&H3, g_H3);
    cudaGetSymbolAddress((void**)&cnt, g_cnt);
    cudaGetSymbolAddress((void**)&offs, g_offs);
    cudaGetSymbolAddress((void**)&cur, g_cur);
    cudaGetSymbolAddress((void**)&psrc, g_psrc);
    cudaGetSymbolAddress((void**)&pval, g_pval);

    // ---- CSR build ----
    zero_counts<<<(M + 255) / 256, 256>>>(cnt, M);
    hist_dst<<<(E + 255) / 256, 256>>>(e_dst, cnt, E);
    scan_offsets<<<1, 1024>>>(cnt, offs, cur, M);
    scatter_edges<<<(E + 255) / 256, 256>>>(e_src, e_dst, A_vals, cur, psrc, pval, E);

    // ---- fused projections: H1 = xW1, H2 = xW2, H3 = xW3 ----
    dim3 gemmGrid(6, (M + BM - 1) / BM);
    sgemm3<<<gemmGrid, 256>>>(x, W1, W2, W3, H1, H2, H3, M);

    // ---- Horner SpMM chain ----
    const int spmmBlocks = (M + 3) / 4;
    spmm_csr<<<spmmBlocks, 256>>>(H3, H2, psrc, pval, offs, M, 0);   // H2 += A H3
    spmm_csr<<<spmmBlocks, 256>>>(H2, H1, psrc, pval, offs, M, 0);   // H1 += A H2
    spmm_csr<<<spmmBlocks, 256>>>(H1, out, psrc, pval, offs, M, 1);  // out = relu(A H1 / 3)
}

// round 4
// speedup vs baseline: 2.6510x; 1.4711x over previous
#include <cuda_runtime.h>
#include <cuda_bf16.h>
#include <cstdint>

#define NNODES 10000
#define FDIM   256
#define NEDGES 320000

// -------- scratch (device globals; no allocation allowed) --------
__device__ float g_H1[NNODES * FDIM];
__device__ float g_H2[NNODES * FDIM];
__device__ float g_H3[NNODES * FDIM];
__device__ int   g_cnt[NNODES];
__device__ int   g_offs[NNODES + 1];
__device__ int   g_cur[NNODES];
__device__ int   g_psrc[NEDGES];
__device__ float g_pval[NEDGES];

// ============================================================================
// Tensor-core triple GEMM via mma.sync (bf16 split: hi*hi + hi*lo + lo*hi).
// CTA tile 128x128, BK=64 chunks, 8 warps in 4x2 (warp tile 32x64).
// grid = (79 m-tiles, 2 n-halves, 3 weights), 256 threads.
// ============================================================================
#define A_STRIDE 72    // 64 + 8 bf16 pad  -> 144B row stride (conflict-free ldmatrix)
#define B_STRIDE 136   // 128 + 8 bf16 pad -> 272B row stride
#define SM_AH 0
#define SM_AL (SM_AH + 128 * A_STRIDE * 2)     // 18432
#define SM_BH (SM_AL + 128 * A_STRIDE * 2)     // 36864
#define SM_BL (SM_BH + 64 * B_STRIDE * 2)      // 54272
#define SM_GEMM_TOTAL (SM_BL + 64 * B_STRIDE * 2)  // 71680

__device__ __forceinline__ uint32_t smem_u32(const void* p) {
    uint32_t a;
    asm("{ .reg .u64 t; cvta.to.shared.u64 t, %1; cvt.u32.u64 %0, t; }"
        : "=r"(a) : "l"(p));
    return a;
}

__device__ __forceinline__ void ldsm_x4(uint32_t* r, uint32_t addr) {
    asm volatile("ldmatrix.sync.aligned.m8n8.x4.shared.b16 {%0,%1,%2,%3}, [%4];"
                 : "=r"(r[0]), "=r"(r[1]), "=r"(r[2]), "=r"(r[3]) : "r"(addr));
}
__device__ __forceinline__ void ldsm_x4_t(uint32_t* r, uint32_t addr) {
    asm volatile("ldmatrix.sync.aligned.m8n8.x4.trans.shared.b16 {%0,%1,%2,%3}, [%4];"
                 : "=r"(r[0]), "=r"(r[1]), "=r"(r[2]), "=r"(r[3]) : "r"(addr));
}
__device__ __forceinline__ void mma_bf16(float* d, const uint32_t* a, const uint32_t* b) {
    asm volatile(
        "mma.sync.aligned.m16n8k16.row.col.f32.bf16.bf16.f32 "
        "{%0,%1,%2,%3}, {%4,%5,%6,%7}, {%8,%9}, {%0,%1,%2,%3};"
        : "+f"(d[0]), "+f"(d[1]), "+f"(d[2]), "+f"(d[3])
        : "r"(a[0]), "r"(a[1]), "r"(a[2]), "r"(a[3]), "r"(b[0]), "r"(b[1]));
}

__device__ __forceinline__ uint32_t pack_hi(float x, float y) {
    __nv_bfloat16 hx = __float2bfloat16_rn(x);
    __nv_bfloat16 hy = __float2bfloat16_rn(y);
    return (uint32_t)__bfloat16_as_ushort(hx) | ((uint32_t)__bfloat16_as_ushort(hy) << 16);
}
__device__ __forceinline__ uint32_t pack_lo(float x, float y) {
    __nv_bfloat16 hx = __float2bfloat16_rn(x);
    __nv_bfloat16 hy = __float2bfloat16_rn(y);
    __nv_bfloat16 lx = __float2bfloat16_rn(x - __bfloat162float(hx));
    __nv_bfloat16 ly = __float2bfloat16_rn(y - __bfloat162float(hy));
    return (uint32_t)__bfloat16_as_ushort(lx) | ((uint32_t)__bfloat16_as_ushort(ly) << 16);
}

__global__ __launch_bounds__(256, 2) void gemm_mma3(
    const float* __restrict__ X,
    const float* __restrict__ Wa, const float* __restrict__ Wb, const float* __restrict__ Wc,
    float* __restrict__ Ca, float* __restrict__ Cb, float* __restrict__ Cc, int M)
{
    extern __shared__ char smem[];
    const uint32_t sb = smem_u32(smem);
    const int tid = threadIdx.x;
    const int wid = tid >> 5;
    const int lane = tid & 31;

    const int bm = blockIdx.x * 128;
    const int n0 = blockIdx.y * 128;
    const int which = blockIdx.z;
    const float* W = (which == 0) ? Wa : (which == 1) ? Wb : Wc;
    float*       C = (which == 0) ? Ca : (which == 1) ? Cb : Cc;

    const int wm = wid & 3;         // warp row: 32 rows
    const int wn = wid >> 2;        // warp col: 64 cols

    float acc[2][8][4];
    #pragma unroll
    for (int i = 0; i < 2; ++i)
        #pragma unroll
        for (int j = 0; j < 8; ++j)
            #pragma unroll
            for (int k = 0; k < 4; ++k) acc[i][j][k] = 0.f;

    // precomputed ldmatrix lane addressing pieces
    const int l8 = lane & 7, lg = lane >> 3;
    // A: row = fragbase + l8 + (lg&1)*8 ; col = kk + (lg>>1)*8
    const int a_row_off = l8 + (lg & 1) * 8;
    const int a_col_off = (lg >> 1) * 8;
    // B(trans): krow = kk + (lg&1)*8 + l8 ; ncol = nbase + (lg>>1)*8
    const int b_k_off = (lg & 1) * 8 + l8;
    const int b_n_off = (lg >> 1) * 8;

    for (int ch = 0; ch < 4; ++ch) {
        const int k0 = ch * 64;

        // ---- stage A chunk: x[bm:bm+128, k0:k0+64] -> bf16 hi/lo ----
        #pragma unroll
        for (int it = 0; it < 8; ++it) {
            int idx = tid + it * 256;
            int row = idx >> 4;
            int col = (idx & 15) << 2;
            float4 v = make_float4(0.f, 0.f, 0.f, 0.f);
            if (bm + row < M)
                v = *reinterpret_cast<const float4*>(X + (size_t)(bm + row) * 256 + k0 + col);
            uint32_t off = (uint32_t)(row * A_STRIDE + col) * 2;
            *reinterpret_cast<uint2*>(smem + SM_AH + off) =
                make_uint2(pack_hi(v.x, v.y), pack_hi(v.z, v.w));
            *reinterpret_cast<uint2*>(smem + SM_AL + off) =
                make_uint2(pack_lo(v.x, v.y), pack_lo(v.z, v.w));
        }
        // ---- stage B chunk: W[k0:k0+64, n0:n0+128] ----
        #pragma unroll
        for (int it = 0; it < 8; ++it) {
            int idx = tid + it * 256;
            int kr = idx >> 5;
            int nc = (idx & 31) << 2;
            float4 v = *reinterpret_cast<const float4*>(W + (size_t)(k0 + kr) * 256 + n0 + nc);
            uint32_t off = (uint32_t)(kr * B_STRIDE + nc) * 2;
            *reinterpret_cast<uint2*>(smem + SM_BH + off) =
                make_uint2(pack_hi(v.x, v.y), pack_hi(v.z, v.w));
            *reinterpret_cast<uint2*>(smem + SM_BL + off) =
                make_uint2(pack_lo(v.x, v.y), pack_lo(v.z, v.w));
        }
        __syncthreads();

        #pragma unroll
        for (int ks = 0; ks < 4; ++ks) {
            const int kk = ks * 16;
            uint32_t ah[2][4], al[2][4], bf[8][2];

            // load A hi + lo fragments (kept resident)
            #pragma unroll
            for (int fm = 0; fm < 2; ++fm) {
                uint32_t row = (uint32_t)(wm * 32 + fm * 16 + a_row_off);
                uint32_t col = (uint32_t)(kk + a_col_off);
                uint32_t rel = (row * A_STRIDE + col) * 2;
                ldsm_x4(ah[fm], sb + SM_AH + rel);
                ldsm_x4(al[fm], sb + SM_AL + rel);
            }
            // B hi -> pass1 (ah*bh) and pass3 (al*bh)
            #pragma unroll
            for (int p = 0; p < 4; ++p) {
                uint32_t krow = (uint32_t)(kk + b_k_off);
                uint32_t ncol = (uint32_t)(wn * 64 + p * 16 + b_n_off);
                ldsm_x4_t(&bf[p * 2][0], sb + SM_BH + (krow * B_STRIDE + ncol) * 2);
            }
            #pragma unroll
            for (int fm = 0; fm < 2; ++fm)
                #pragma unroll
                for (int fn = 0; fn < 8; ++fn) {
                    mma_bf16(acc[fm][fn], ah[fm], bf[fn]);
                }
            #pragma unroll
            for (int fm = 0; fm < 2; ++fm)
                #pragma unroll
                for (int fn = 0; fn < 8; ++fn) {
                    mma_bf16(acc[fm][fn], al[fm], bf[fn]);
                }
            // B lo -> pass2 (ah*bl)
            #pragma unroll
            for (int p = 0; p < 4; ++p) {
                uint32_t krow = (uint32_t)(kk + b_k_off);
                uint32_t ncol = (uint32_t)(wn * 64 + p * 16 + b_n_off);
                ldsm_x4_t(&bf[p * 2][0], sb + SM_BL + (krow * B_STRIDE + ncol) * 2);
            }
            #pragma unroll
            for (int fm = 0; fm < 2; ++fm)
                #pragma unroll
                for (int fn = 0; fn < 8; ++fn) {
                    mma_bf16(acc[fm][fn], ah[fm], bf[fn]);
                }
        }
        __syncthreads();
    }

    // ---- epilogue: direct stores ----
    const int qr = lane >> 2;           // 0..7
    const int qc = (lane & 3) * 2;      // 0,2,4,6
    #pragma unroll
    for (int fm = 0; fm < 2; ++fm) {
        int r0 = bm + wm * 32 + fm * 16 + qr;
        #pragma unroll
        for (int fn = 0; fn < 8; ++fn) {
            int cc = n0 + wn * 64 + fn * 8 + qc;
            if (r0 < M)
                *reinterpret_cast<float2*>(C + (size_t)r0 * 256 + cc) =
                    make_float2(acc[fm][fn][0], acc[fm][fn][1]);
            if (r0 + 8 < M)
                *reinterpret_cast<float2*>(C + (size_t)(r0 + 8) * 256 + cc) =
                    make_float2(acc[fm][fn][2], acc[fm][fn][3]);
        }
    }
}

// ============================================================================
// CSR build
// ============================================================================
__global__ void zero_counts(int* __restrict__ cnt, int n)
{
    int i = blockIdx.x * blockDim.x + threadIdx.x;
    if (i < n) cnt[i] = 0;
}

__global__ void hist_dst(const int* __restrict__ dst, int* __restrict__ cnt, int E)
{
    int e = blockIdx.x * blockDim.x + threadIdx.x;
    if (e < E) atomicAdd(&cnt[dst[e]], 1);
}

// Single-block exclusive scan: serial per-thread + shfl warp scan (2 syncs).
__global__ __launch_bounds__(1024) void scan_offsets(
    const int* __restrict__ cnt, int* __restrict__ offs, int* __restrict__ cur, int n)
{
    const int ipt = (n + 1023) >> 10;          // 10 for n=10000 (supports n<=16384)
    int t = threadIdx.x;
    int base = t * ipt;

    int local[16];
    int sum = 0;
    for (int j = 0; j < ipt; ++j) {
        int i = base + j;
        int v = (i < n) ? cnt[i] : 0;
        local[j] = sum;
        sum += v;
    }

    __shared__ int wsum[32];
    int lane = t & 31, wrp = t >> 5;
    int s = sum;
    #pragma unroll
    for (int d = 1; d < 32; d <<= 1) {
        int o = __shfl_up_sync(0xffffffff, s, d);
        if (lane >= d) s += o;
    }
    if (lane == 31) wsum[wrp] = s;
    __syncthreads();
    if (wrp == 0) {
        int ws = wsum[lane];
        #pragma unroll
        for (int d = 1; d < 32; d <<= 1) {
            int o = __shfl_up_sync(0xffffffff, ws, d);
            if (lane >= d) ws += o;
        }
        wsum[lane] = ws;
    }
    __syncthreads();
    int thrExcl = ((wrp == 0) ? 0 : wsum[wrp - 1]) + (s - sum);

    for (int j = 0; j < ipt; ++j) {
        int i = base + j;
        if (i < n) { int e = thrExcl + local[j]; offs[i] = e; cur[i] = e; }
    }
    if (t == 1023) offs[n] = thrExcl + sum;
}

__global__ void scatter_edges(
    const int* __restrict__ src, const int* __restrict__ dst,
    const float* __restrict__ vals, int* __restrict__ cur,
    int* __restrict__ psrc, float* __restrict__ pval, int E)
{
    int e = blockIdx.x * blockDim.x + threadIdx.x;
    if (e < E) {
        int pos = atomicAdd(&cur[dst[e]], 1);
        psrc[pos] = src[e];
        pval[pos] = vals[e];
    }
}

// ============================================================================
// CSR SpMM gather (no atomics). 64 threads/node (float4 each).
// mode 0: out[n] += sum val*h[src] ; mode 1: out[n] = relu(sum/3)
// ============================================================================
__global__ __launch_bounds__(256) void spmm_csr(
    const float* __restrict__ h, float* __restrict__ outp,
    const int* __restrict__ psrc, const float* __restrict__ pval,
    const int* __restrict__ offs, int M, int finalMode)
{
    int node = blockIdx.x * 4 + (threadIdx.x >> 6);
    if (node >= M) return;
    int c = (threadIdx.x & 63) << 2;

    int beg = __ldg(offs + node);
    int end = __ldg(offs + node + 1);

    float4 acc;
    if (finalMode) acc = make_float4(0.f, 0.f, 0.f, 0.f);
    else           acc = *reinterpret_cast<const float4*>(outp + (size_t)node * FDIM + c);

    int e = beg;
    for (; e + 4 <= end; e += 4) {
        int   s0 = __ldg(psrc + e),     s1 = __ldg(psrc + e + 1);
        int   s2 = __ldg(psrc + e + 2), s3 = __ldg(psrc + e + 3);
        float v0 = __ldg(pval + e),     v1 = __ldg(pval + e + 1);
        float v2 = __ldg(pval + e + 2), v3 = __ldg(pval + e + 3);
        float4 r0 = *reinterpret_cast<const float4*>(h + (size_t)s0 * FDIM + c);
        float4 r1 = *reinterpret_cast<const float4*>(h + (size_t)s1 * FDIM + c);
        float4 r2 = *reinterpret_cast<const float4*>(h + (size_t)s2 * FDIM + c);
        float4 r3 = *reinterpret_cast<const float4*>(h + (size_t)s3 * FDIM + c);
        acc.x = fmaf(v0, r0.x, acc.x); acc.y = fmaf(v0, r0.y, acc.y);
        acc.z = fmaf(v0, r0.z, acc.z); acc.w = fmaf(v0, r0.w, acc.w);
        acc.x = fmaf(v1, r1.x, acc.x); acc.y = fmaf(v1, r1.y, acc.y);
        acc.z = fmaf(v1, r1.z, acc.z); acc.w = fmaf(v1, r1.w, acc.w);
        acc.x = fmaf(v2, r2.x, acc.x); acc.y = fmaf(v2, r2.y, acc.y);
        acc.z = fmaf(v2, r2.z, acc.z); acc.w = fmaf(v2, r2.w, acc.w);
        acc.x = fmaf(v3, r3.x, acc.x); acc.y = fmaf(v3, r3.y, acc.y);
        acc.z = fmaf(v3, r3.z, acc.z); acc.w = fmaf(v3, r3.w, acc.w);
    }
    for (; e < end; ++e) {
        int s = __ldg(psrc + e);
        float v = __ldg(pval + e);
        float4 r = *reinterpret_cast<const float4*>(h + (size_t)s * FDIM + c);
        acc.x = fmaf(v, r.x, acc.x); acc.y = fmaf(v, r.y, acc.y);
        acc.z = fmaf(v, r.z, acc.z); acc.w = fmaf(v, r.w, acc.w);
    }

    if (finalMode) {
        const float third = 1.0f / 3.0f;
        acc.x = fmaxf(acc.x * third, 0.f);
        acc.y = fmaxf(acc.y * third, 0.f);
        acc.z = fmaxf(acc.z * third, 0.f);
        acc.w = fmaxf(acc.w * third, 0.f);
    }
    *reinterpret_cast<float4*>(outp + (size_t)node * FDIM + c) = acc;
}

// ============================================================================
// out = relu( (1/3) * A*(h1 + A*(h2 + A*h3)) ),  hk = x @ Wk   (Horner)
// ============================================================================
extern "C" void kernel_launch(void* const* d_in, const int* in_sizes, int n_in,
                              void* d_out, int out_size)
{
    const float* x      = (const float*)d_in[0];
    const float* A_vals = (const float*)d_in[1];
    const float* W1     = (const float*)d_in[2];
    const float* W2     = (const float*)d_in[3];
    const float* W3     = (const float*)d_in[4];
    const int*   e_src  = (const int*)d_in[5];
    const int*   e_dst  = (const int*)d_in[6];
    float* out = (float*)d_out;

    const int M = in_sizes[0] / FDIM;      // 10000
    const int E = in_sizes[5];             // 320000

    float *H1, *H2, *H3; int *cnt, *offs, *cur, *psrc; float *pval;
    cudaGetSymbolAddress((void**)&H1, g_H1);
    cudaGetSymbolAddress((void**)&H2, g_H2);
    cudaGetSymbolAddress((void**)&H3, g_H3);
    cudaGetSymbolAddress((void**)&cnt, g_cnt);
    cudaGetSymbolAddress((void**)&offs, g_offs);
    cudaGetSymbolAddress((void**)&cur, g_cur);
    cudaGetSymbolAddress((void**)&psrc, g_psrc);
    cudaGetSymbolAddress((void**)&pval, g_pval);

    // ---- CSR build ----
    zero_counts<<<(M + 255) / 256, 256>>>(cnt, M);
    hist_dst<<<(E + 255) / 256, 256>>>(e_dst, cnt, E);
    scan_offsets<<<1, 1024>>>(cnt, offs, cur, M);
    scatter_edges<<<(E + 255) / 256, 256>>>(e_src, e_dst, A_vals, cur, psrc, pval, E);

    // ---- tensor-core projections: Hk = x @ Wk ----
    cudaFuncSetAttribute(gemm_mma3, cudaFuncAttributeMaxDynamicSharedMemorySize,
                         SM_GEMM_TOTAL);
    dim3 gemmGrid((M + 127) / 128, 2, 3);
    gemm_mma3<<<gemmGrid, 256, SM_GEMM_TOTAL>>>(x, W1, W2, W3, H1, H2, H3, M);

    // ---- Horner SpMM chain ----
    const int spmmBlocks = (M + 3) / 4;
    spmm_csr<<<spmmBlocks, 256>>>(H3, H2, psrc, pval, offs, M, 0);   // H2 += A H3
    spmm_csr<<<spmmBlocks, 256>>>(H2, H1, psrc, pval, offs, M, 0);   // H1 += A H2
    spmm_csr<<<spmmBlocks, 256>>>(H1, out, psrc, pval, offs, M, 1);  // out = relu(A H1 / 3)
}

// round 7
// speedup vs baseline: 2.6836x; 1.0123x over previous
#include <cuda_runtime.h>
#include <cuda_bf16.h>
#include <cstdint>

#define NNODES 10000
#define FDIM   256
#define NEDGES 320000

// -------- scratch (device globals; no allocation allowed) --------
__device__ float g_H1[NNODES * FDIM];
__device__ float g_H2[NNODES * FDIM];
__device__ float g_H3[NNODES * FDIM];
__device__ int   g_cnt[NNODES];
__device__ int   g_offs[NNODES + 1];
__device__ int   g_cur[NNODES];
__device__ int2  g_edge[NEDGES];       // interleaved {src, val-as-int}

// ============================================================================
// Tensor-core triple GEMM via mma.sync (bf16 split: hi*hi + hi*lo + lo*hi).
// CTA tile 128x128, BK=64 chunks, 8 warps in 4x2 (warp tile 32x64).
// grid = (79 m-tiles, 2 n-halves, 3 weights), 256 threads.
// ============================================================================
#define A_STRIDE 72
#define B_STRIDE 136
#define SM_AH 0
#define SM_AL (SM_AH + 128 * A_STRIDE * 2)
#define SM_BH (SM_AL + 128 * A_STRIDE * 2)
#define SM_BL (SM_BH + 64 * B_STRIDE * 2)
#define SM_GEMM_TOTAL (SM_BL + 64 * B_STRIDE * 2)  // 71680

__device__ __forceinline__ uint32_t smem_u32(const void* p) {
    uint32_t a;
    asm("{ .reg .u64 t; cvta.to.shared.u64 t, %1; cvt.u32.u64 %0, t; }"
        : "=r"(a) : "l"(p));
    return a;
}

__device__ __forceinline__ void ldsm_x4(uint32_t* r, uint32_t addr) {
    asm volatile("ldmatrix.sync.aligned.m8n8.x4.shared.b16 {%0,%1,%2,%3}, [%4];"
                 : "=r"(r[0]), "=r"(r[1]), "=r"(r[2]), "=r"(r[3]) : "r"(addr));
}
__device__ __forceinline__ void ldsm_x4_t(uint32_t* r, uint32_t addr) {
    asm volatile("ldmatrix.sync.aligned.m8n8.x4.trans.shared.b16 {%0,%1,%2,%3}, [%4];"
                 : "=r"(r[0]), "=r"(r[1]), "=r"(r[2]), "=r"(r[3]) : "r"(addr));
}
__device__ __forceinline__ void mma_bf16(float* d, const uint32_t* a, const uint32_t* b) {
    asm volatile(
        "mma.sync.aligned.m16n8k16.row.col.f32.bf16.bf16.f32 "
        "{%0,%1,%2,%3}, {%4,%5,%6,%7}, {%8,%9}, {%0,%1,%2,%3};"
        : "+f"(d[0]), "+f"(d[1]), "+f"(d[2]), "+f"(d[3])
        : "r"(a[0]), "r"(a[1]), "r"(a[2]), "r"(a[3]), "r"(b[0]), "r"(b[1]));
}

__device__ __forceinline__ uint32_t pack_hi(float x, float y) {
    __nv_bfloat16 hx = __float2bfloat16_rn(x);
    __nv_bfloat16 hy = __float2bfloat16_rn(y);
    return (uint32_t)__bfloat16_as_ushort(hx) | ((uint32_t)__bfloat16_as_ushort(hy) << 16);
}
__device__ __forceinline__ uint32_t pack_lo(float x, float y) {
    __nv_bfloat16 hx = __float2bfloat16_rn(x);
    __nv_bfloat16 hy = __float2bfloat16_rn(y);
    __nv_bfloat16 lx = __float2bfloat16_rn(x - __bfloat162float(hx));
    __nv_bfloat16 ly = __float2bfloat16_rn(y - __bfloat162float(hy));
    return (uint32_t)__bfloat16_as_ushort(lx) | ((uint32_t)__bfloat16_as_ushort(ly) << 16);
}

__global__ __launch_bounds__(256, 2) void gemm_mma3(
    const float* __restrict__ X,
    const float* __restrict__ Wa, const float* __restrict__ Wb, const float* __restrict__ Wc,
    float* __restrict__ Ca, float* __restrict__ Cb, float* __restrict__ Cc, int M)
{
    extern __shared__ char smem[];
    const uint32_t sb = smem_u32(smem);
    const int tid = threadIdx.x;
    const int wid = tid >> 5;
    const int lane = tid & 31;

    const int bm = blockIdx.x * 128;
    const int n0 = blockIdx.y * 128;
    const int which = blockIdx.z;
    const float* W = (which == 0) ? Wa : (which == 1) ? Wb : Wc;
    float*       C = (which == 0) ? Ca : (which == 1) ? Cb : Cc;

    const int wm = wid & 3;
    const int wn = wid >> 2;

    float acc[2][8][4];
    #pragma unroll
    for (int i = 0; i < 2; ++i)
        #pragma unroll
        for (int j = 0; j < 8; ++j)
            #pragma unroll
            for (int k = 0; k < 4; ++k) acc[i][j][k] = 0.f;

    const int l8 = lane & 7, lg = lane >> 3;
    const int a_row_off = l8 + (lg & 1) * 8;
    const int a_col_off = (lg >> 1) * 8;
    const int b_k_off = (lg & 1) * 8 + l8;
    const int b_n_off = (lg >> 1) * 8;

    for (int ch = 0; ch < 4; ++ch) {
        const int k0 = ch * 64;

        #pragma unroll
        for (int it = 0; it < 8; ++it) {
            int idx = tid + it * 256;
            int row = idx >> 4;
            int col = (idx & 15) << 2;
            float4 v = make_float4(0.f, 0.f, 0.f, 0.f);
            if (bm + row < M)
                v = *reinterpret_cast<const float4*>(X + (size_t)(bm + row) * 256 + k0 + col);
            uint32_t off = (uint32_t)(row * A_STRIDE + col) * 2;
            *reinterpret_cast<uint2*>(smem + SM_AH + off) =
                make_uint2(pack_hi(v.x, v.y), pack_hi(v.z, v.w));
            *reinterpret_cast<uint2*>(smem + SM_AL + off) =
                make_uint2(pack_lo(v.x, v.y), pack_lo(v.z, v.w));
        }
        #pragma unroll
        for (int it = 0; it < 8; ++it) {
            int idx = tid + it * 256;
            int kr = idx >> 5;
            int nc = (idx & 31) << 2;
            float4 v = *reinterpret_cast<const float4*>(W + (size_t)(k0 + kr) * 256 + n0 + nc);
            uint32_t off = (uint32_t)(kr * B_STRIDE + nc) * 2;
            *reinterpret_cast<uint2*>(smem + SM_BH + off) =
                make_uint2(pack_hi(v.x, v.y), pack_hi(v.z, v.w));
            *reinterpret_cast<uint2*>(smem + SM_BL + off) =
                make_uint2(pack_lo(v.x, v.y), pack_lo(v.z, v.w));
        }
        __syncthreads();

        #pragma unroll
        for (int ks = 0; ks < 4; ++ks) {
            const int kk = ks * 16;
            uint32_t ah[2][4], al[2][4], bf[8][2];

            #pragma unroll
            for (int fm = 0; fm < 2; ++fm) {
                uint32_t row = (uint32_t)(wm * 32 + fm * 16 + a_row_off);
                uint32_t col = (uint32_t)(kk + a_col_off);
                uint32_t rel = (row * A_STRIDE + col) * 2;
                ldsm_x4(ah[fm], sb + SM_AH + rel);
                ldsm_x4(al[fm], sb + SM_AL + rel);
            }
            #pragma unroll
            for (int p = 0; p < 4; ++p) {
                uint32_t krow = (uint32_t)(kk + b_k_off);
                uint32_t ncol = (uint32_t)(wn * 64 + p * 16 + b_n_off);
                ldsm_x4_t(&bf[p * 2][0], sb + SM_BH + (krow * B_STRIDE + ncol) * 2);
            }
            #pragma unroll
            for (int fm = 0; fm < 2; ++fm)
                #pragma unroll
                for (int fn = 0; fn < 8; ++fn) mma_bf16(acc[fm][fn], ah[fm], bf[fn]);
            #pragma unroll
            for (int fm = 0; fm < 2; ++fm)
                #pragma unroll
                for (int fn = 0; fn < 8; ++fn) mma_bf16(acc[fm][fn], al[fm], bf[fn]);
            #pragma unroll
            for (int p = 0; p < 4; ++p) {
                uint32_t krow = (uint32_t)(kk + b_k_off);
                uint32_t ncol = (uint32_t)(wn * 64 + p * 16 + b_n_off);
                ldsm_x4_t(&bf[p * 2][0], sb + SM_BL + (krow * B_STRIDE + ncol) * 2);
            }
            #pragma unroll
            for (int fm = 0; fm < 2; ++fm)
                #pragma unroll
                for (int fn = 0; fn < 8; ++fn) mma_bf16(acc[fm][fn], ah[fm], bf[fn]);
        }
        __syncthreads();
    }

    const int qr = lane >> 2;
    const int qc = (lane & 3) * 2;
    #pragma unroll
    for (int fm = 0; fm < 2; ++fm) {
        int r0 = bm + wm * 32 + fm * 16 + qr;
        #pragma unroll
        for (int fn = 0; fn < 8; ++fn) {
            int cc = n0 + wn * 64 + fn * 8 + qc;
            if (r0 < M)
                *reinterpret_cast<float2*>(C + (size_t)r0 * 256 + cc) =
                    make_float2(acc[fm][fn][0], acc[fm][fn][1]);
            if (r0 + 8 < M)
                *reinterpret_cast<float2*>(C + (size_t)(r0 + 8) * 256 + cc) =
                    make_float2(acc[fm][fn][2], acc[fm][fn][3]);
        }
    }
}

// ============================================================================
// CSR build
// ============================================================================
__global__ void zero_counts(int* __restrict__ cnt, int n)
{
    int i = blockIdx.x * blockDim.x + threadIdx.x;
    if (i < n) cnt[i] = 0;
}

// 4 edges per thread for ILP
__global__ __launch_bounds__(256) void hist_dst(
    const int* __restrict__ dst, int* __restrict__ cnt, int E)
{
    int b = (blockIdx.x * blockDim.x + threadIdx.x) * 4;
    #pragma unroll
    for (int j = 0; j < 4; ++j) {
        int e = b + j;
        if (e < E) atomicAdd(&cnt[__ldg(dst + e)], 1);
    }
}

// Single-block exclusive scan: serial per-thread + shfl warp scan (2 syncs).
__global__ __launch_bounds__(1024) void scan_offsets(
    const int* __restrict__ cnt, int* __restrict__ offs, int* __restrict__ cur, int n)
{
    const int ipt = (n + 1023) >> 10;
    int t = threadIdx.x;
    int base = t * ipt;

    int local[16];
    int sum = 0;
    for (int j = 0; j < ipt; ++j) {
        int i = base + j;
        int v = (i < n) ? cnt[i] : 0;
        local[j] = sum;
        sum += v;
    }

    __shared__ int wsum[32];
    int lane = t & 31, wrp = t >> 5;
    int s = sum;
    #pragma unroll
    for (int d = 1; d < 32; d <<= 1) {
        int o = __shfl_up_sync(0xffffffff, s, d);
        if (lane >= d) s += o;
    }
    if (lane == 31) wsum[wrp] = s;
    __syncthreads();
    if (wrp == 0) {
        int ws = wsum[lane];
        #pragma unroll
        for (int d = 1; d < 32; d <<= 1) {
            int o = __shfl_up_sync(0xffffffff, ws, d);
            if (lane >= d) ws += o;
        }
        wsum[lane] = ws;
    }
    __syncthreads();
    int thrExcl = ((wrp == 0) ? 0 : wsum[wrp - 1]) + (s - sum);

    for (int j = 0; j < ipt; ++j) {
        int i = base + j;
        if (i < n) { int e = thrExcl + local[j]; offs[i] = e; cur[i] = e; }
    }
    if (t == 1023) offs[n] = thrExcl + sum;
}

// 4 edges per thread; single int2 store per edge.
__global__ __launch_bounds__(256) void scatter_edges(
    const int* __restrict__ src, const int* __restrict__ dst,
    const float* __restrict__ vals, int* __restrict__ cur,
    int2* __restrict__ edges, int E)
{
    int b = (blockIdx.x * blockDim.x + threadIdx.x) * 4;
    #pragma unroll
    for (int j = 0; j < 4; ++j) {
        int e = b + j;
        if (e < E) {
            int d = __ldg(dst + e);
            int s = __ldg(src + e);
            float v = __ldg(vals + e);
            int pos = atomicAdd(&cur[d], 1);
            edges[pos] = make_int2(s, __float_as_int(v));
        }
    }
}

// ============================================================================
// CSR SpMM gather (no atomics). 64 threads/node (float4 each).
// mode 0: out[n] += sum val*h[src] ; mode 1: out[n] = relu(sum/3)
// ============================================================================
__global__ __launch_bounds__(256) void spmm_csr(
    const float* __restrict__ h, float* __restrict__ outp,
    const int2* __restrict__ edges, const int* __restrict__ offs, int M, int finalMode)
{
    int node = blockIdx.x * 4 + (threadIdx.x >> 6);
    if (node >= M) return;
    int c = (threadIdx.x & 63) << 2;

    int beg = __ldg(offs + node);
    int end = __ldg(offs + node + 1);

    float4 acc;
    if (finalMode) acc = make_float4(0.f, 0.f, 0.f, 0.f);
    else           acc = *reinterpret_cast<const float4*>(outp + (size_t)node * FDIM + c);

    int e = beg;
    for (; e + 4 <= end; e += 4) {
        int2 e0 = __ldg(edges + e),     e1 = __ldg(edges + e + 1);
        int2 e2 = __ldg(edges + e + 2), e3 = __ldg(edges + e + 3);
        float v0 = __int_as_float(e0.y), v1 = __int_as_float(e1.y);
        float v2 = __int_as_float(e2.y), v3 = __int_as_float(e3.y);
        float4 r0 = *reinterpret_cast<const float4*>(h + (size_t)e0.x * FDIM + c);
        float4 r1 = *reinterpret_cast<const float4*>(h + (size_t)e1.x * FDIM + c);
        float4 r2 = *reinterpret_cast<const float4*>(h + (size_t)e2.x * FDIM + c);
        float4 r3 = *reinterpret_cast<const float4*>(h + (size_t)e3.x * FDIM + c);
        acc.x = fmaf(v0, r0.x, acc.x); acc.y = fmaf(v0, r0.y, acc.y);
        acc.z = fmaf(v0, r0.z, acc.z); acc.w = fmaf(v0, r0.w, acc.w);
        acc.x = fmaf(v1, r1.x, acc.x); acc.y = fmaf(v1, r1.y, acc.y);
        acc.z = fmaf(v1, r1.z, acc.z); acc.w = fmaf(v1, r1.w, acc.w);
        acc.x = fmaf(v2, r2.x, acc.x); acc.y = fmaf(v2, r2.y, acc.y);
        acc.z = fmaf(v2, r2.z, acc.z); acc.w = fmaf(v2, r2.w, acc.w);
        acc.x = fmaf(v3, r3.x, acc.x); acc.y = fmaf(v3, r3.y, acc.y);
        acc.z = fmaf(v3, r3.z, acc.z); acc.w = fmaf(v3, r3.w, acc.w);
    }
    for (; e < end; ++e) {
        int2 ed = __ldg(edges + e);
        float v = __int_as_float(ed.y);
        float4 r = *reinterpret_cast<const float4*>(h + (size_t)ed.x * FDIM + c);
        acc.x = fmaf(v, r.x, acc.x); acc.y = fmaf(v, r.y, acc.y);
        acc.z = fmaf(v, r.z, acc.z); acc.w = fmaf(v, r.w, acc.w);
    }

    if (finalMode) {
        const float third = 1.0f / 3.0f;
        acc.x = fmaxf(acc.x * third, 0.f);
        acc.y = fmaxf(acc.y * third, 0.f);
        acc.z = fmaxf(acc.z * third, 0.f);
        acc.w = fmaxf(acc.w * third, 0.f);
    }
    *reinterpret_cast<float4*>(outp + (size_t)node * FDIM + c) = acc;
}

// ============================================================================
// out = relu( (1/3) * A*(h1 + A*(h2 + A*h3)) ),  hk = x @ Wk   (Horner)
// Single stream (multi-stream fork-join hard-fails this harness's container).
// ============================================================================
extern "C" void kernel_launch(void* const* d_in, const int* in_sizes, int n_in,
                              void* d_out, int out_size)
{
    const float* x      = (const float*)d_in[0];
    const float* A_vals = (const float*)d_in[1];
    const float* W1     = (const float*)d_in[2];
    const float* W2     = (const float*)d_in[3];
    const float* W3     = (const float*)d_in[4];
    const int*   e_src  = (const int*)d_in[5];
    const int*   e_dst  = (const int*)d_in[6];
    float* out = (float*)d_out;

    const int M = in_sizes[0] / FDIM;      // 10000
    const int E = in_sizes[5];             // 320000

    float *H1, *H2, *H3; int *cnt, *offs, *cur; int2 *edges;
    cudaGetSymbolAddress((void**)&H1, g_H1);
    cudaGetSymbolAddress((void**)&H2, g_H2);
    cudaGetSymbolAddress((void**)&H3, g_H3);
    cudaGetSymbolAddress((void**)&cnt, g_cnt);
    cudaGetSymbolAddress((void**)&offs, g_offs);
    cudaGetSymbolAddress((void**)&cur, g_cur);
    cudaGetSymbolAddress((void**)&edges, g_edge);

    // ---- CSR build ----
    zero_counts<<<(M + 255) / 256, 256>>>(cnt, M);
    hist_dst<<<(E + 1023) / 1024, 256>>>(e_dst, cnt, E);
    scan_offsets<<<1, 1024>>>(cnt, offs, cur, M);
    scatter_edges<<<(E + 1023) / 1024, 256>>>(e_src, e_dst, A_vals, cur, edges, E);

    // ---- tensor-core projections: Hk = x @ Wk ----
    cudaFuncSetAttribute(gemm_mma3, cudaFuncAttributeMaxDynamicSharedMemorySize,
                         SM_GEMM_TOTAL);
    dim3 gemmGrid((M + 127) / 128, 2, 3);
    gemm_mma3<<<gemmGrid, 256, SM_GEMM_TOTAL>>>(x, W1, W2, W3, H1, H2, H3, M);

    // ---- Horner SpMM chain ----
    const int spmmBlocks = (M + 3) / 4;
    spmm_csr<<<spmmBlocks, 256>>>(H3, H2, edges, offs, M, 0);   // H2 += A H3
    spmm_csr<<<spmmBlocks, 256>>>(H2, H1, edges, offs, M, 0);   // H1 += A H2
    spmm_csr<<<spmmBlocks, 256>>>(H1, out, edges, offs, M, 1);  // out = relu(A H1 / 3)
}